// round 9
// baseline (speedup 1.0000x reference)
#include <cuda_runtime.h>
#include <cuda_bf16.h>

#define NF   256     // feature dim
#define DEG  32      // neighbors per node
#define MM   33      // subgraph size (target + neighbors)
#define BMAX 10240   // max batch (actual B=10000)
#define WPB  8       // warps per block in weights_kernel

// Scratch (allocation-free: __device__ globals)
__device__ __align__(16) float g_mix[(size_t)BMAX * NF];
__device__ float g_c0[BMAX];
__device__ float g_w[(size_t)BMAX * MM];
__device__ int   g_sid[(size_t)BMAX * MM];

__device__ __forceinline__ unsigned f2tf32(float f) {
    unsigned u;
    asm("cvt.rna.tf32.f32 %0, %1;" : "=r"(u) : "f"(f));
    return u;
}

__device__ __forceinline__ void mma_tf32_16n8k8(
    float d[4], const unsigned a[4], const unsigned b[2], const float c[4])
{
    asm volatile(
        "mma.sync.aligned.m16n8k8.row.col.f32.tf32.tf32.f32 "
        "{%0,%1,%2,%3}, {%4,%5,%6,%7}, {%8,%9}, {%10,%11,%12,%13};\n"
        : "=f"(d[0]), "=f"(d[1]), "=f"(d[2]), "=f"(d[3])
        : "r"(a[0]), "r"(a[1]), "r"(a[2]), "r"(a[3]),
          "r"(b[0]), "r"(b[1]),
          "f"(c[0]), "f"(c[1]), "f"(c[2]), "f"(c[3]));
}

// ---------------------------------------------------------------------------
// Kernel A1: per-target weights. One warp per target.
// 64-slot hash of the 33 subgraph ids, built with PARALLEL atomicCAS insert
// (atomicMin keeps the FIRST occurrence -> dedup for free). Membership is
// one probe per adjacency entry; adjacency rows software-pipelined.
// ---------------------------------------------------------------------------
__global__ void __launch_bounds__(256) weights_kernel(
    const int* __restrict__ adj,    // [N_NODES, DEG]
    const int* __restrict__ bn,     // [B]
    int B)
{
    __shared__ int tbl_key[WPB][64];
    __shared__ int tbl_col[WPB][64];
    __shared__ int s_ids[WPB][MM];
    __shared__ unsigned long long s_mask[WPB][MM];
    __shared__ float s_c[WPB][MM];

    const int w    = threadIdx.x >> 5;
    const int lane = threadIdx.x & 31;
    const int b    = blockIdx.x * WPB + w;
    if (b >= B) return;                     // whole warp exits together

    const int v = bn[b];
    tbl_key[w][lane]      = -1;
    tbl_key[w][lane + 32] = -1;
    tbl_col[w][lane]      = 0xFF;
    tbl_col[w][lane + 32] = 0xFF;
    s_ids[w][lane + 1] = adj[(size_t)v * DEG + lane];
    if (lane == 0) s_ids[w][0] = v;
    __syncwarp();

    // ---- parallel hash insert: lane j inserts id_j (2 rounds for j=32) ----
    #pragma unroll
    for (int r = 0; r < 2; r++) {
        int j = lane + r * 32;
        if (j < MM) {
            int id = s_ids[w][j];
            unsigned h = ((unsigned)id * 0x9E3779B1u) >> 26;
            while (true) {
                int old = atomicCAS(&tbl_key[w][h], -1, id);
                if (old == -1 || old == id) {
                    atomicMin(&tbl_col[w][h], j);   // first occurrence wins
                    break;
                }
                h = (h + 1) & 63;
            }
        }
    }
    __syncwarp();

    // ---- valid mask vm: id's recorded column == own position j ----
    unsigned long long vm;
    {
        unsigned lo, hi = 0;
        {
            int id = s_ids[w][lane + 1 - 1];   // j = lane (ids 0..31)
            id = s_ids[w][lane];
            unsigned h = ((unsigned)id * 0x9E3779B1u) >> 26;
            while (tbl_key[w][h] != id) h = (h + 1) & 63;
            lo = __ballot_sync(0xffffffffu, tbl_col[w][h] == lane);
        }
        if (lane == 0) {
            int id = s_ids[w][32];
            unsigned h = ((unsigned)id * 0x9E3779B1u) >> 26;
            while (tbl_key[w][h] != id) h = (h + 1) & 63;
            hi = (tbl_col[w][h] == 32) ? 1u : 0u;
        }
        hi = __shfl_sync(0xffffffffu, hi, 0);
        vm = (unsigned long long)lo | ((unsigned long long)hi << 32);
    }

    // ---- membership + degree, rows pipelined ----
    int deg_own = 0;   // in-degree of column `lane`
    int deg32   = 0;   // column 32 (lane 0 only)
    int a = adj[(size_t)s_ids[w][0] * DEG + lane];
    for (int i = 0; i < MM; i++) {
        int a_next = 0;
        if (i + 1 < MM)
            a_next = adj[(size_t)s_ids[w][i + 1] * DEG + lane];

        // probe: which column does this entry hit (first occurrence only)?
        int col = -1;
        unsigned h = ((unsigned)a * 0x9E3779B1u) >> 26;
        while (true) {
            int k = tbl_key[w][h];
            if (k == a) { col = tbl_col[w][h]; break; }
            if (k == -1) break;
            h = (h + 1) & 63;
        }
        unsigned long long m =
            (unsigned long long)__reduce_or_sync(0xffffffffu,
                (col >= 0 && col < 32) ? (1u << col) : 0u) |
            ((unsigned long long)__reduce_or_sync(0xffffffffu,
                (col == 32) ? 1u : 0u) << 32);
        if (!((vm >> i) & 1ull)) m = 0ull;      // invalid (dup) row
        if (lane == 0) s_mask[w][i] = m;
        deg_own += (int)((m >> lane) & 1ull);
        if (lane == 0) deg32 += (int)((m >> 32) & 1ull);
        a = a_next;
    }

    // ---- c_j = rsqrt(max(deg,1)) ----
    s_c[w][lane] = rsqrtf((float)(deg_own < 1 ? 1 : deg_own));
    if (lane == 0) s_c[w][32] = rsqrtf((float)(deg32 < 1 ? 1 : deg32));
    __syncwarp();

    // ---- w_src[i] = c_i * sum_{j in row_i} c_j  (rows sparse; row 0 dense) ----
    #pragma unroll
    for (int r = 0; r < 2; r++) {
        int i = lane + r * 32;
        if (i < MM) {
            unsigned long long m = s_mask[w][i];
            float sum = 0.0f;
            while (m) {
                int j = __ffsll((long long)m) - 1;
                sum += s_c[w][j];
                m &= (m - 1);
            }
            g_w[(size_t)b * MM + i]   = s_c[w][i] * sum;
            g_sid[(size_t)b * MM + i] = s_ids[w][i];
        }
    }
    if (lane == 0) g_c0[b] = s_c[w][0];
}

// ---------------------------------------------------------------------------
// Kernel A2: mix[b] = sum_i w[b,i] * feat[sid[b,i]]  — streaming gather.
// 4 targets per 256-thread CTA; 64 threads (float4 lanes) per target.
// ---------------------------------------------------------------------------
#define GRP 4
__global__ void __launch_bounds__(256) mix_kernel(
    const float* __restrict__ feat, int B)
{
    __shared__ float s_w[GRP][MM];
    __shared__ int   s_id[GRP][MM];

    const int t  = threadIdx.x;
    const int b0 = blockIdx.x * GRP;

    for (int idx = t; idx < GRP * MM; idx += 256) {
        int g = idx / MM, i = idx - g * MM;
        int b = b0 + g;
        if (b < B) {
            s_w[g][i]  = g_w[(size_t)b * MM + i];
            s_id[g][i] = g_sid[(size_t)b * MM + i];
        }
    }
    __syncthreads();

    const int g = t >> 6;
    const int j = t & 63;        // float4 column index
    const int b = b0 + g;
    if (b >= B) return;

    float4 acc0 = make_float4(0.f, 0.f, 0.f, 0.f);
    float4 acc1 = make_float4(0.f, 0.f, 0.f, 0.f);
    #pragma unroll
    for (int i = 0; i < MM; i += 2) {
        {
            float  wv = s_w[g][i];
            float4 f4 = *reinterpret_cast<const float4*>(
                            &feat[(size_t)s_id[g][i] * NF + j * 4]);
            acc0.x = fmaf(wv, f4.x, acc0.x);
            acc0.y = fmaf(wv, f4.y, acc0.y);
            acc0.z = fmaf(wv, f4.z, acc0.z);
            acc0.w = fmaf(wv, f4.w, acc0.w);
        }
        if (i + 1 < MM) {
            float  wv = s_w[g][i + 1];
            float4 f4 = *reinterpret_cast<const float4*>(
                            &feat[(size_t)s_id[g][i + 1] * NF + j * 4]);
            acc1.x = fmaf(wv, f4.x, acc1.x);
            acc1.y = fmaf(wv, f4.y, acc1.y);
            acc1.z = fmaf(wv, f4.z, acc1.z);
            acc1.w = fmaf(wv, f4.w, acc1.w);
        }
    }
    float4 r;
    r.x = acc0.x + acc1.x;  r.y = acc0.y + acc1.y;
    r.z = acc0.z + acc1.z;  r.w = acc0.w + acc1.w;
    *reinterpret_cast<float4*>(&g_mix[(size_t)b * NF + j * 4]) = r;
}

// ---------------------------------------------------------------------------
// Kernel B: out = relu(mix @ W + c0 * feat[batch_nodes])
// tf32 mma.sync m16n8k8. CTA tile 64x128, BK=16, 256 threads (R8, unchanged).
// ---------------------------------------------------------------------------
#define BM 64
#define BN 128
#define BK 16

__global__ void __launch_bounds__(256) gemm_kernel(
    const float* __restrict__ W,      // [NF, NF] row-major (k, n)
    const float* __restrict__ feat,   // [N_NODES, NF]
    const int*   __restrict__ bn,     // [B]
    float*       __restrict__ out,    // [B, NF]
    int B)
{
    __shared__ __align__(16) unsigned sA[BK][BM + 4];   // tf32, transposed [k][m]
    __shared__ __align__(16) unsigned sB[BK][BN + 4];   // tf32, [k][n]

    const int tid  = threadIdx.x;
    const int lane = tid & 31;
    const int wid  = tid >> 5;
    const int bm0  = blockIdx.y * BM;
    const int bn0  = blockIdx.x * BN;

    const int wm  = wid >> 2;        // 0..1 : warp row (32 rows)
    const int wn  = wid & 3;         // 0..3 : warp col (32 cols)
    const int g   = lane >> 2;       // 0..7
    const int tig = lane & 3;        // 0..3

    const int arow = tid >> 2;       // 0..63
    const int acol = (tid & 3) * 4;  // 0,4,8,12
    const int brow = tid >> 5;       // 0..7 (and +8)
    const int bcol = (tid & 31) * 4; // 0..124

    const int  agr = bm0 + arow;
    const bool aok = (agr < B);
    const float* aP  = &g_mix[(size_t)agr * NF + acol];
    const float* bP0 = &W[(size_t)brow * NF + bn0 + bcol];
    const float* bP1 = &W[(size_t)(brow + 8) * NF + bn0 + bcol];

    float acc[2][4][4];
    #pragma unroll
    for (int mt = 0; mt < 2; mt++)
        #pragma unroll
        for (int nt = 0; nt < 4; nt++)
            #pragma unroll
            for (int r = 0; r < 4; r++) acc[mt][nt][r] = 0.0f;

    float4 nA = aok ? *reinterpret_cast<const float4*>(aP)
                    : make_float4(0.f, 0.f, 0.f, 0.f);
    float4 nB0 = *reinterpret_cast<const float4*>(bP0);
    float4 nB1 = *reinterpret_cast<const float4*>(bP1);

    #pragma unroll 1
    for (int kk = 0; kk < NF; kk += BK) {
        sA[acol + 0][arow] = f2tf32(nA.x);
        sA[acol + 1][arow] = f2tf32(nA.y);
        sA[acol + 2][arow] = f2tf32(nA.z);
        sA[acol + 3][arow] = f2tf32(nA.w);
        sB[brow][bcol + 0] = f2tf32(nB0.x);
        sB[brow][bcol + 1] = f2tf32(nB0.y);
        sB[brow][bcol + 2] = f2tf32(nB0.z);
        sB[brow][bcol + 3] = f2tf32(nB0.w);
        sB[brow + 8][bcol + 0] = f2tf32(nB1.x);
        sB[brow + 8][bcol + 1] = f2tf32(nB1.y);
        sB[brow + 8][bcol + 2] = f2tf32(nB1.z);
        sB[brow + 8][bcol + 3] = f2tf32(nB1.w);
        __syncthreads();

        if (kk + BK < NF) {
            nA = aok ? *reinterpret_cast<const float4*>(aP + kk + BK)
                     : make_float4(0.f, 0.f, 0.f, 0.f);
            nB0 = *reinterpret_cast<const float4*>(bP0 + (size_t)(kk + BK) * NF);
            nB1 = *reinterpret_cast<const float4*>(bP1 + (size_t)(kk + BK) * NF);
        }

        #pragma unroll
        for (int ks = 0; ks < 2; ks++) {
            const int k0 = ks * 8;
            unsigned afr[2][4];
            #pragma unroll
            for (int mt = 0; mt < 2; mt++) {
                const int ar = wm * 32 + mt * 16;
                afr[mt][0] = sA[k0 + tig    ][ar + g    ];
                afr[mt][1] = sA[k0 + tig    ][ar + g + 8];
                afr[mt][2] = sA[k0 + tig + 4][ar + g    ];
                afr[mt][3] = sA[k0 + tig + 4][ar + g + 8];
            }
            unsigned bfr[4][2];
            #pragma unroll
            for (int nt = 0; nt < 4; nt++) {
                const int nb = wn * 32 + nt * 8;
                bfr[nt][0] = sB[k0 + tig    ][nb + g];
                bfr[nt][1] = sB[k0 + tig + 4][nb + g];
            }
            #pragma unroll
            for (int mt = 0; mt < 2; mt++)
                #pragma unroll
                for (int nt = 0; nt < 4; nt++)
                    mma_tf32_16n8k8(acc[mt][nt], afr[mt], bfr[nt], acc[mt][nt]);
        }
        __syncthreads();
    }

    #pragma unroll
    for (int mt = 0; mt < 2; mt++) {
        #pragma unroll
        for (int half = 0; half < 2; half++) {
            const int gr = bm0 + wm * 32 + mt * 16 + g + half * 8;
            if (gr >= B) continue;
            const int   node = bn[gr];
            const float cc   = g_c0[gr];
            #pragma unroll
            for (int nt = 0; nt < 4; nt++) {
                const int gc = bn0 + wn * 32 + nt * 8 + tig * 2;
                float2 h2 = *reinterpret_cast<const float2*>(
                                &feat[(size_t)node * NF + gc]);
                float2 r;
                r.x = fmaxf(acc[mt][nt][half * 2 + 0] + cc * h2.x, 0.0f);
                r.y = fmaxf(acc[mt][nt][half * 2 + 1] + cc * h2.y, 0.0f);
                *reinterpret_cast<float2*>(&out[(size_t)gr * NF + gc]) = r;
            }
        }
    }
}

// ---------------------------------------------------------------------------
extern "C" void kernel_launch(void* const* d_in, const int* in_sizes, int n_in,
                              void* d_out, int out_size)
{
    const float* feat = (const float*)d_in[0];   // node_features [50000,256]
    const float* W    = (const float*)d_in[1];   // weight [256,256]
    const int*   adj  = (const int*)d_in[2];     // adj [50000,32]
    const int*   bn   = (const int*)d_in[3];     // batch_nodes [B]
    float*       out  = (float*)d_out;

    const int B = in_sizes[3];

    weights_kernel<<<(B + WPB - 1) / WPB, 256>>>(adj, bn, B);
    mix_kernel<<<(B + GRP - 1) / GRP, 256>>>(feat, B);

    dim3 grid(NF / BN, (B + BM - 1) / BM);
    gemm_kernel<<<grid, 256>>>(W, feat, bn, out, B);
}

// round 11
// speedup vs baseline: 1.4373x; 1.4373x over previous
#include <cuda_runtime.h>
#include <cuda_bf16.h>

#define NF   256     // feature dim
#define DEG  32      // neighbors per node
#define MM   33      // subgraph size (target + neighbors)
#define BMAX 10240   // max batch (actual B=10000)
#define WPB  8       // warps per block in weights_kernel

// Scratch (allocation-free: __device__ globals)
__device__ __align__(16) float g_mix[(size_t)BMAX * NF];
__device__ float g_c0[BMAX];
__device__ float g_w[(size_t)BMAX * MM];
__device__ int   g_sid[(size_t)BMAX * MM];

__device__ __forceinline__ unsigned f2tf32(float f) {
    unsigned u;
    asm("cvt.rna.tf32.f32 %0, %1;" : "=r"(u) : "f"(f));
    return u;
}

__device__ __forceinline__ void mma_tf32_16n8k8(
    float d[4], const unsigned a[4], const unsigned b[2], const float c[4])
{
    asm volatile(
        "mma.sync.aligned.m16n8k8.row.col.f32.tf32.tf32.f32 "
        "{%0,%1,%2,%3}, {%4,%5,%6,%7}, {%8,%9}, {%10,%11,%12,%13};\n"
        : "=f"(d[0]), "=f"(d[1]), "=f"(d[2]), "=f"(d[3])
        : "r"(a[0]), "r"(a[1]), "r"(a[2]), "r"(a[3]),
          "r"(b[0]), "r"(b[1]),
          "f"(c[0]), "f"(c[1]), "f"(c[2]), "f"(c[3]));
}

// ---------------------------------------------------------------------------
// Kernel A1: per-target weights. One warp per target.
// Branch-free: rank-sort the 33 ids (fixed 33-iter compare loop, stable ->
// dedup free), then membership = fixed 6-step binary search per adjacency
// entry. No atomics, no data-dependent loops anywhere.
// ---------------------------------------------------------------------------
__global__ void __launch_bounds__(256) weights_kernel(
    const int* __restrict__ adj,    // [N_NODES, DEG]
    const int* __restrict__ bn,     // [B]
    int B)
{
    __shared__ int s_ids[WPB][MM];
    __shared__ int s_sid[WPB][64];   // sorted ids, padded INT_MAX
    __shared__ int s_col[WPB][64];   // original column of sorted entry

    const int w    = threadIdx.x >> 5;
    const int lane = threadIdx.x & 31;
    const int b    = blockIdx.x * WPB + w;
    if (b >= B) return;                     // whole warp exits together

    // ---- load subgraph ids: col 0 = v, cols 1..32 = adj[v] ----
    const int v = bn[b];
    const int av = adj[(size_t)v * DEG + lane];
    s_ids[w][lane + 1] = av;
    if (lane == 0) s_ids[w][0] = v;
    s_sid[w][lane]      = 0x7FFFFFFF;
    s_sid[w][lane + 32] = 0x7FFFFFFF;
    __syncwarp();

    const int own  = s_ids[w][lane];        // lane j owns column j (0..31)
    const int id32 = s_ids[w][32];          // column 32 handled uniformly

    // ---- rank (stable: tie-break by column index) + dedup, fixed 33 iters ----
    int  rank = 0, rank32 = 0;
    bool dup = false;
    #pragma unroll
    for (int r = 0; r < MM; r++) {
        int  idr = s_ids[w][r];
        bool eq  = (idr == own);
        rank   += (idr < own) || (eq && r < lane);
        dup    |= (eq && r < lane);
        rank32 += (idr < id32) || (idr == id32 && r < 32);
    }
    const unsigned vm_lo = ~__ballot_sync(0xffffffffu, dup);
    const bool     vm_hi = (__ballot_sync(0xffffffffu, own == id32) == 0u);

    // scatter into sorted table (ranks are all distinct)
    s_sid[w][rank] = own;
    s_col[w][rank] = lane;
    if (lane == 0) { s_sid[w][rank32] = id32; s_col[w][rank32] = 32; }
    __syncwarp();

    // ---- membership: 33 rows; per row, each lane resolves one adjacency
    //      entry via branch-free lower_bound over the sorted 64-slot table ----
    unsigned my_lo = 0, my_hi = 0;          // mask of row `lane`
    unsigned r32_lo = 0, r32_hi = 0;        // mask of row 32 (uniform)
    int deg_own = 0, deg32 = 0;

    int a = adj[(size_t)s_ids[w][0] * DEG + lane];
    #pragma unroll 1
    for (int i = 0; i < MM; i++) {
        int a_next = 0;
        if (i + 1 < MM)
            a_next = adj[(size_t)s_ids[w][i + 1] * DEG + lane];

        // lower_bound: pos = #elements < a  (6 predicated steps)
        int pos = 0;
        #pragma unroll
        for (int S = 32; S >= 1; S >>= 1)
            pos += (s_sid[w][pos + S - 1] < a) ? S : 0;
        const bool match = (s_sid[w][pos] == a);   // first occurrence if dup
        const int  col   = s_col[w][pos];

        unsigned lo = __reduce_or_sync(0xffffffffu,
                          (match && col < 32) ? (1u << col) : 0u);
        unsigned hi = __reduce_or_sync(0xffffffffu,
                          (match && col == 32) ? 1u : 0u);

        const bool rvalid = (i < 32) ? ((vm_lo >> i) & 1u) : vm_hi;
        if (!rvalid) { lo = 0u; hi = 0u; }

        deg_own += (lo >> lane) & 1u;
        deg32   += hi;

        if (i == 32)           { r32_lo = lo; r32_hi = hi; }
        else if (lane == i)    { my_lo  = lo; my_hi  = hi; }
        a = a_next;
    }

    // ---- c = rsqrt(max(deg,1)) ----
    const float c_own = rsqrtf((float)(deg_own < 1 ? 1 : deg_own));
    const float c32   = rsqrtf((float)(deg32   < 1 ? 1 : deg32));

    // ---- w_src[i] = c_i * sum_{j in row_i} c_j : fixed 32-step shfl dot ----
    float sum = 0.0f, sum32 = 0.0f;
    #pragma unroll
    for (int j = 0; j < 32; j++) {
        float cj = __shfl_sync(0xffffffffu, c_own, j);
        if ((my_lo  >> j) & 1u) sum   += cj;
        if ((r32_lo >> j) & 1u) sum32 += cj;
    }
    if (my_hi)  sum   += c32;
    if (r32_hi) sum32 += c32;

    g_w  [(size_t)b * MM + lane] = c_own * sum;
    g_sid[(size_t)b * MM + lane] = own;
    if (lane == 0) {
        g_w  [(size_t)b * MM + 32] = c32 * sum32;
        g_sid[(size_t)b * MM + 32] = id32;
        g_c0[b] = c_own;                     // c of column 0 (target)
    }
}

// ---------------------------------------------------------------------------
// Kernel A2: mix[b] = sum_i w[b,i] * feat[sid[b,i]]  — streaming gather.
// 4 targets per 256-thread CTA; 64 threads (float4 lanes) per target.
// ---------------------------------------------------------------------------
#define GRP 4
__global__ void __launch_bounds__(256) mix_kernel(
    const float* __restrict__ feat, int B)
{
    __shared__ float s_w[GRP][MM];
    __shared__ int   s_id[GRP][MM];

    const int t  = threadIdx.x;
    const int b0 = blockIdx.x * GRP;

    for (int idx = t; idx < GRP * MM; idx += 256) {
        int g = idx / MM, i = idx - g * MM;
        int b = b0 + g;
        if (b < B) {
            s_w[g][i]  = g_w[(size_t)b * MM + i];
            s_id[g][i] = g_sid[(size_t)b * MM + i];
        }
    }
    __syncthreads();

    const int g = t >> 6;
    const int j = t & 63;        // float4 column index
    const int b = b0 + g;
    if (b >= B) return;

    float4 acc0 = make_float4(0.f, 0.f, 0.f, 0.f);
    float4 acc1 = make_float4(0.f, 0.f, 0.f, 0.f);
    #pragma unroll
    for (int i = 0; i < MM; i += 2) {
        {
            float  wv = s_w[g][i];
            float4 f4 = *reinterpret_cast<const float4*>(
                            &feat[(size_t)s_id[g][i] * NF + j * 4]);
            acc0.x = fmaf(wv, f4.x, acc0.x);
            acc0.y = fmaf(wv, f4.y, acc0.y);
            acc0.z = fmaf(wv, f4.z, acc0.z);
            acc0.w = fmaf(wv, f4.w, acc0.w);
        }
        if (i + 1 < MM) {
            float  wv = s_w[g][i + 1];
            float4 f4 = *reinterpret_cast<const float4*>(
                            &feat[(size_t)s_id[g][i + 1] * NF + j * 4]);
            acc1.x = fmaf(wv, f4.x, acc1.x);
            acc1.y = fmaf(wv, f4.y, acc1.y);
            acc1.z = fmaf(wv, f4.z, acc1.z);
            acc1.w = fmaf(wv, f4.w, acc1.w);
        }
    }
    float4 r;
    r.x = acc0.x + acc1.x;  r.y = acc0.y + acc1.y;
    r.z = acc0.z + acc1.z;  r.w = acc0.w + acc1.w;
    *reinterpret_cast<float4*>(&g_mix[(size_t)b * NF + j * 4]) = r;
}

// ---------------------------------------------------------------------------
// Kernel B: out = relu(mix @ W + c0 * feat[batch_nodes])
// tf32 mma.sync m16n8k8. CTA tile 64x128, BK=16, 256 threads (R8, unchanged).
// ---------------------------------------------------------------------------
#define BM 64
#define BN 128
#define BK 16

__global__ void __launch_bounds__(256) gemm_kernel(
    const float* __restrict__ W,      // [NF, NF] row-major (k, n)
    const float* __restrict__ feat,   // [N_NODES, NF]
    const int*   __restrict__ bn,     // [B]
    float*       __restrict__ out,    // [B, NF]
    int B)
{
    __shared__ __align__(16) unsigned sA[BK][BM + 4];   // tf32, transposed [k][m]
    __shared__ __align__(16) unsigned sB[BK][BN + 4];   // tf32, [k][n]

    const int tid  = threadIdx.x;
    const int lane = tid & 31;
    const int wid  = tid >> 5;
    const int bm0  = blockIdx.y * BM;
    const int bn0  = blockIdx.x * BN;

    const int wm  = wid >> 2;        // 0..1 : warp row (32 rows)
    const int wn  = wid & 3;         // 0..3 : warp col (32 cols)
    const int g   = lane >> 2;       // 0..7
    const int tig = lane & 3;        // 0..3

    const int arow = tid >> 2;       // 0..63
    const int acol = (tid & 3) * 4;  // 0,4,8,12
    const int brow = tid >> 5;       // 0..7 (and +8)
    const int bcol = (tid & 31) * 4; // 0..124

    const int  agr = bm0 + arow;
    const bool aok = (agr < B);
    const float* aP  = &g_mix[(size_t)agr * NF + acol];
    const float* bP0 = &W[(size_t)brow * NF + bn0 + bcol];
    const float* bP1 = &W[(size_t)(brow + 8) * NF + bn0 + bcol];

    float acc[2][4][4];
    #pragma unroll
    for (int mt = 0; mt < 2; mt++)
        #pragma unroll
        for (int nt = 0; nt < 4; nt++)
            #pragma unroll
            for (int r = 0; r < 4; r++) acc[mt][nt][r] = 0.0f;

    float4 nA = aok ? *reinterpret_cast<const float4*>(aP)
                    : make_float4(0.f, 0.f, 0.f, 0.f);
    float4 nB0 = *reinterpret_cast<const float4*>(bP0);
    float4 nB1 = *reinterpret_cast<const float4*>(bP1);

    #pragma unroll 1
    for (int kk = 0; kk < NF; kk += BK) {
        sA[acol + 0][arow] = f2tf32(nA.x);
        sA[acol + 1][arow] = f2tf32(nA.y);
        sA[acol + 2][arow] = f2tf32(nA.z);
        sA[acol + 3][arow] = f2tf32(nA.w);
        sB[brow][bcol + 0] = f2tf32(nB0.x);
        sB[brow][bcol + 1] = f2tf32(nB0.y);
        sB[brow][bcol + 2] = f2tf32(nB0.z);
        sB[brow][bcol + 3] = f2tf32(nB0.w);
        sB[brow + 8][bcol + 0] = f2tf32(nB1.x);
        sB[brow + 8][bcol + 1] = f2tf32(nB1.y);
        sB[brow + 8][bcol + 2] = f2tf32(nB1.z);
        sB[brow + 8][bcol + 3] = f2tf32(nB1.w);
        __syncthreads();

        if (kk + BK < NF) {
            nA = aok ? *reinterpret_cast<const float4*>(aP + kk + BK)
                     : make_float4(0.f, 0.f, 0.f, 0.f);
            nB0 = *reinterpret_cast<const float4*>(bP0 + (size_t)(kk + BK) * NF);
            nB1 = *reinterpret_cast<const float4*>(bP1 + (size_t)(kk + BK) * NF);
        }

        #pragma unroll
        for (int ks = 0; ks < 2; ks++) {
            const int k0 = ks * 8;
            unsigned afr[2][4];
            #pragma unroll
            for (int mt = 0; mt < 2; mt++) {
                const int ar = wm * 32 + mt * 16;
                afr[mt][0] = sA[k0 + tig    ][ar + g    ];
                afr[mt][1] = sA[k0 + tig    ][ar + g + 8];
                afr[mt][2] = sA[k0 + tig + 4][ar + g    ];
                afr[mt][3] = sA[k0 + tig + 4][ar + g + 8];
            }
            unsigned bfr[4][2];
            #pragma unroll
            for (int nt = 0; nt < 4; nt++) {
                const int nb = wn * 32 + nt * 8;
                bfr[nt][0] = sB[k0 + tig    ][nb + g];
                bfr[nt][1] = sB[k0 + tig + 4][nb + g];
            }
            #pragma unroll
            for (int mt = 0; mt < 2; mt++)
                #pragma unroll
                for (int nt = 0; nt < 4; nt++)
                    mma_tf32_16n8k8(acc[mt][nt], afr[mt], bfr[nt], acc[mt][nt]);
        }
        __syncthreads();
    }

    #pragma unroll
    for (int mt = 0; mt < 2; mt++) {
        #pragma unroll
        for (int half = 0; half < 2; half++) {
            const int gr = bm0 + wm * 32 + mt * 16 + g + half * 8;
            if (gr >= B) continue;
            const int   node = bn[gr];
            const float cc   = g_c0[gr];
            #pragma unroll
            for (int nt = 0; nt < 4; nt++) {
                const int gc = bn0 + wn * 32 + nt * 8 + tig * 2;
                float2 h2 = *reinterpret_cast<const float2*>(
                                &feat[(size_t)node * NF + gc]);
                float2 r;
                r.x = fmaxf(acc[mt][nt][half * 2 + 0] + cc * h2.x, 0.0f);
                r.y = fmaxf(acc[mt][nt][half * 2 + 1] + cc * h2.y, 0.0f);
                *reinterpret_cast<float2*>(&out[(size_t)gr * NF + gc]) = r;
            }
        }
    }
}

// ---------------------------------------------------------------------------
extern "C" void kernel_launch(void* const* d_in, const int* in_sizes, int n_in,
                              void* d_out, int out_size)
{
    const float* feat = (const float*)d_in[0];   // node_features [50000,256]
    const float* W    = (const float*)d_in[1];   // weight [256,256]
    const int*   adj  = (const int*)d_in[2];     // adj [50000,32]
    const int*   bn   = (const int*)d_in[3];     // batch_nodes [B]
    float*       out  = (float*)d_out;

    const int B = in_sizes[3];

    weights_kernel<<<(B + WPB - 1) / WPB, 256>>>(adj, bn, B);
    mix_kernel<<<(B + GRP - 1) / GRP, 256>>>(feat, B);

    dim3 grid(NF / BN, (B + BM - 1) / BM);
    gemm_kernel<<<grid, 256>>>(W, feat, bn, out, B);
}